// round 7
// baseline (speedup 1.0000x reference)
#include <cuda_runtime.h>
#include <stdint.h>

// CoarseMatching, single-read fused design via column-argmax.
// conf [N, L, S] fp32, L = 4800, S = 4800.
// Outputs (concatenated fp32): mconf [N*L], mask_v [N*L], all_j_ids [N*L].
//
// Fused pass (one read): per column (value, first attaining row, dup flag)
// in registers, merged globally with two packed 64-bit atomicMax; per row
// plain fmaxf rowmax (value only).
// F1 (per column): candidate (colargmax, j) if colmax==rowmax[l]+borders+THR;
//   atomicMin for first-j. Duplicated column max (detected exactly) ->
//   warp-cooperative column rescan enumerating all attaining rows.
// F2 (per row): emit outputs.

#define THR  0.2f
#define BRM  2
#define H0   60
#define W0   80
#define H1   60
#define W1   80
#define LSZ  (H0 * W0)   // 4800
#define SSZ  (H1 * W1)   // 4800
#define MAXN 16
#define RPB  32
#define SLOTS 5          // ceil(1200 float4 / 256 threads)

typedef unsigned long long ull;

__device__ ull      g_key1 [MAXN * SSZ];   // (bits<<32) | (0xFFFFFFFF - l): max -> value, then smallest l
__device__ ull      g_key2 [MAXN * SSZ];   // (bits<<32) | (dup?0xFFFFFFFF:l): detects multiple attaining rows
__device__ float    g_rowmax[MAXN * LSZ];
__device__ unsigned g_best [MAXN * LSZ];   // first matching j per row (atomicMin), 0xFFFFFFFF = none

__device__ __forceinline__ void updc(float& cmv, int& cml, unsigned& dupm,
                                     float v, int l, unsigned bit) {
    const bool gt = (v > cmv);
    const bool eq = (v == cmv);
    if (gt) { cml = l; dupm &= ~bit; }
    if (eq) { dupm |= bit; }
    cmv = fmaxf(cmv, v);
}

__global__ __launch_bounds__(256) void fused_kernel(const float* __restrict__ conf) {
    __shared__ float s_rm[RPB][8];

    const int tid    = threadIdx.x;
    const int groups = LSZ / RPB;                   // 150
    const int n      = blockIdx.x / groups;
    const int lbase  = (blockIdx.x % groups) * RPB;
    const int w      = tid >> 5, lane = tid & 31;
    const bool full  = (tid < (SSZ / 4 - 4 * 256)); // owns 5th slot

    float    cmv[SLOTS][4];
    int      cml[SLOTS][4];
    unsigned dupm = 0u;
    #pragma unroll
    for (int k = 0; k < SLOTS; ++k)
        #pragma unroll
        for (int c = 0; c < 4; ++c) { cmv[k][c] = 0.f; cml[k][c] = 0; }

    const float4* base = reinterpret_cast<const float4*>(
        conf + ((size_t)n * LSZ + (size_t)lbase) * SSZ);

    #pragma unroll 1
    for (int r = 0; r < RPB; ++r) {
        const float4* row = base + (size_t)r * (SSZ / 4);
        const int l = lbase + r;
        float m0 = 0.f, m1 = 0.f, m2 = 0.f, m3 = 0.f;

        #pragma unroll
        for (int k = 0; k < SLOTS; ++k) {
            const int i = tid + k * 256;
            if (k < SLOTS - 1 || full) {
                const float4 v = row[i];
                m0 = fmaxf(m0, v.x);
                m1 = fmaxf(m1, v.y);
                m2 = fmaxf(m2, v.z);
                m3 = fmaxf(m3, v.w);
                updc(cmv[k][0], cml[k][0], dupm, v.x, l, 1u << (k * 4 + 0));
                updc(cmv[k][1], cml[k][1], dupm, v.y, l, 1u << (k * 4 + 1));
                updc(cmv[k][2], cml[k][2], dupm, v.z, l, 1u << (k * 4 + 2));
                updc(cmv[k][3], cml[k][3], dupm, v.w, l, 1u << (k * 4 + 3));
            }
        }

        float m = fmaxf(fmaxf(m0, m1), fmaxf(m2, m3));
        #pragma unroll
        for (int off = 16; off; off >>= 1)
            m = fmaxf(m, __shfl_down_sync(0xFFFFFFFFu, m, off));
        if (lane == 0) s_rm[r][w] = m;
    }
    __syncthreads();

    if (tid < RPB) {
        float m = s_rm[tid][0];
        #pragma unroll
        for (int w2 = 1; w2 < 8; ++w2) m = fmaxf(m, s_rm[tid][w2]);
        g_rowmax[n * LSZ + lbase + tid] = m;
    }

    // flush per-column state (two packed atomics per owned column)
    #pragma unroll
    for (int k = 0; k < SLOTS; ++k) {
        if (k < SLOTS - 1 || full) {
            #pragma unroll
            for (int c = 0; c < 4; ++c) {
                const int col = (tid + k * 256) * 4 + c;
                const unsigned bits = __float_as_uint(cmv[k][c]);
                const unsigned l    = (unsigned)cml[k][c];
                const bool dup = (dupm >> (k * 4 + c)) & 1u;
                const ull key1 = ((ull)bits << 32) | (ull)(0xFFFFFFFFu - l);
                const ull key2 = ((ull)bits << 32) | (ull)(dup ? 0xFFFFFFFFu : l);
                atomicMax(&g_key1[n * SSZ + col], key1);
                atomicMax(&g_key2[n * SSZ + col], key2);
            }
        }
    }
}

__global__ __launch_bounds__(256) void f1_kernel(const float* __restrict__ conf, int N) {
    const int idx   = blockIdx.x * 256 + threadIdx.x;
    const int total = N * SSZ;
    const int lane  = threadIdx.x & 31;

    int n = 0, j = 0;
    unsigned vbits = 0;
    bool dup = false;

    if (idx < total) {
        n = idx / SSZ; j = idx % SSZ;
        const int sr = j / W1, sc = j % W1;
        if (sr >= BRM && sr < H1 - BRM && sc >= BRM && sc < W1 - BRM) {
            const ull k1 = g_key1[idx];
            vbits = (unsigned)(k1 >> 32);
            const float v = __uint_as_float(vbits);
            if (v > THR) {
                const unsigned l1   = 0xFFFFFFFFu - (unsigned)k1;
                const unsigned low2 = (unsigned)g_key2[idx];
                if (low2 == l1) {
                    // unique attaining row
                    const int lr = (int)l1 / W0, lc = (int)l1 % W0;
                    if (lr >= BRM && lr < H0 - BRM && lc >= BRM && lc < W0 - BRM &&
                        __float_as_uint(g_rowmax[n * LSZ + (int)l1]) == vbits)
                        atomicMin(&g_best[n * LSZ + (int)l1], (unsigned)j);
                } else {
                    dup = true;
                }
            }
        }
    }

    // warp-cooperative exact rescan for the rare duplicated-colmax columns
    unsigned mask = __ballot_sync(0xFFFFFFFFu, dup);
    while (mask) {
        const int src = __ffs(mask) - 1;
        mask &= mask - 1;
        const int      dn = __shfl_sync(0xFFFFFFFFu, n, src);
        const int      dj = __shfl_sync(0xFFFFFFFFu, j, src);
        const unsigned db = __shfl_sync(0xFFFFFFFFu, vbits, src);
        for (int l = lane; l < LSZ; l += 32) {
            if (__float_as_uint(conf[((size_t)dn * LSZ + l) * SSZ + dj]) == db) {
                const int lr = l / W0, lc = l % W0;
                if (lr >= BRM && lr < H0 - BRM && lc >= BRM && lc < W0 - BRM &&
                    __float_as_uint(g_rowmax[dn * LSZ + l]) == db)
                    atomicMin(&g_best[dn * LSZ + l], (unsigned)dj);
            }
        }
    }
}

__global__ __launch_bounds__(256) void f2_kernel(float* __restrict__ out, int N) {
    const int idx = blockIdx.x * 256 + threadIdx.x;
    const int NL  = N * LSZ;
    if (idx >= NL) return;
    const unsigned j = g_best[idx];
    float mconf = 0.f, mv = 0.f, jf = 0.f;
    if (j != 0xFFFFFFFFu) {
        mconf = g_rowmax[idx];
        mv = 1.f;
        jf = (float)j;
    }
    out[idx]          = mconf;
    out[NL + idx]     = mv;
    out[2 * NL + idx] = jf;
}

extern "C" void kernel_launch(void* const* d_in, const int* in_sizes, int n_in,
                              void* d_out, int out_size) {
    const float* conf = (const float*)d_in[0];
    const long long total = (long long)in_sizes[0];
    int N = (int)(total / ((long long)LSZ * (long long)SSZ));
    if (N < 1) N = 1;
    if (N > MAXN) N = MAXN;

    void *p1 = nullptr, *p2 = nullptr, *pb = nullptr;
    cudaGetSymbolAddress(&p1, g_key1);
    cudaGetSymbolAddress(&p2, g_key2);
    cudaGetSymbolAddress(&pb, g_best);
    cudaMemsetAsync(p1, 0,    (size_t)N * SSZ * sizeof(ull));
    cudaMemsetAsync(p2, 0,    (size_t)N * SSZ * sizeof(ull));
    cudaMemsetAsync(pb, 0xFF, (size_t)N * LSZ * sizeof(unsigned));

    fused_kernel<<<N * (LSZ / RPB), 256>>>(conf);
    f1_kernel<<<(N * SSZ + 255) / 256, 256>>>(conf, N);
    f2_kernel<<<(N * LSZ + 255) / 256, 256>>>((float*)d_out, N);
}

// round 8
// speedup vs baseline: 1.9651x; 1.9651x over previous
#include <cuda_runtime.h>
#include <stdint.h>

// CoarseMatching, 2-pass, warp-per-row-pair match.
// conf [N, L, S] fp32, L = 4800, S = 4800.
// Outputs (concatenated fp32): mconf [N*L], mask_v [N*L], all_j_ids [N*L].
//
// Pass 1 (colmax): full read, per-column max via atomicMax on float bits.
// Pass 2 (match): colmax staged in SMEM, border-invalid / (<=THR) columns
//   poisoned to 0xFFFFFFFF. Each warp scans two full rows independently:
//   rowmax fmax chains + one bits==colmax compare per element (rare branch
//   tracks best candidate + first j). match iff best == rowmax.

#define THR  0.2f
#define BRM  2
#define H0   60
#define W0   80
#define H1   60
#define W1   80
#define LSZ  (H0 * W0)   // 4800
#define SSZ  (H1 * W1)   // 4800
#define MAXN 16
#define RPB  16
#define NF4  (SSZ / 4)   // 1200 float4 per row

__device__ unsigned int g_colmax[MAXN * SSZ];

__global__ __launch_bounds__(256) void colmax_kernel(const float* __restrict__ conf) {
    const int n  = blockIdx.z;
    const int i4 = blockIdx.x * blockDim.x + threadIdx.x;
    if (i4 >= NF4) return;
    const int l0 = blockIdx.y * 100;

    const float4* p = reinterpret_cast<const float4*>(
        conf + ((size_t)n * LSZ + (size_t)l0) * SSZ) + i4;

    float4 m = make_float4(0.f, 0.f, 0.f, 0.f);
    #pragma unroll 5
    for (int t = 0; t < 100; ++t) {
        const float4 v = *p;
        m.x = fmaxf(m.x, v.x);
        m.y = fmaxf(m.y, v.y);
        m.z = fmaxf(m.z, v.z);
        m.w = fmaxf(m.w, v.w);
        p += NF4;
    }
    unsigned int* cm = g_colmax + (size_t)n * SSZ + (size_t)i4 * 4;
    atomicMax(cm + 0, __float_as_uint(m.x));
    atomicMax(cm + 1, __float_as_uint(m.y));
    atomicMax(cm + 2, __float_as_uint(m.z));
    atomicMax(cm + 3, __float_as_uint(m.w));
}

// per-float4 candidate/rowmax update for one row
__device__ __forceinline__ void elem_upd(const float4 v, const uint4 c, const int s0,
                                         float& m0, float& m1, float& m2, float& m3,
                                         float& bv, int& bj) {
    m0 = fmaxf(m0, v.x);
    m1 = fmaxf(m1, v.y);
    m2 = fmaxf(m2, v.z);
    m3 = fmaxf(m3, v.w);
    const bool c0 = (__float_as_uint(v.x) == c.x);
    const bool c1 = (__float_as_uint(v.y) == c.y);
    const bool c2 = (__float_as_uint(v.z) == c.z);
    const bool c3 = (__float_as_uint(v.w) == c.w);
    if (c0 | c1 | c2 | c3) {                 // rare (~1 in 1200 float4s)
        if (c0 && v.x > bv) { bv = v.x; bj = s0 + 0; }
        if (c1 && v.y > bv) { bv = v.y; bj = s0 + 1; }
        if (c2 && v.z > bv) { bv = v.z; bj = s0 + 2; }
        if (c3 && v.w > bv) { bv = v.w; bj = s0 + 3; }
    }
}

__device__ __forceinline__ void warp_reduce_row(float& m, float& bv, int& bj) {
    #pragma unroll
    for (int off = 16; off; off >>= 1) {
        m = fmaxf(m, __shfl_down_sync(0xFFFFFFFFu, m, off));
        const float ov = __shfl_down_sync(0xFFFFFFFFu, bv, off);
        const int   oj = __shfl_down_sync(0xFFFFFFFFu, bj, off);
        if (ov > bv || (ov == bv && oj < bj)) { bv = ov; bj = oj; }
    }
}

__global__ __launch_bounds__(256, 6) void match_kernel(const float* __restrict__ conf,
                                                       float* __restrict__ out, int N) {
    __shared__ unsigned s_cm[SSZ];                  // 19.2 KB poisoned colmax

    const int tid    = threadIdx.x;
    const int groups = LSZ / RPB;                   // 300
    const int n      = blockIdx.x / groups;
    const int lbase  = (blockIdx.x % groups) * RPB;
    const int NL     = N * LSZ;
    const int w      = tid >> 5, lane = tid & 31;

    // 16 | 80: all rows of this block share lr.
    const int lr = lbase / W0;
    const bool lr_ok = (lr >= BRM) && (lr < H0 - BRM);

    // Stage colmax into SMEM; poison border-invalid and <=THR columns.
    for (int i = tid; i < NF4; i += 256) {
        uint4 c = *reinterpret_cast<const uint4*>(g_colmax + (size_t)n * SSZ + (size_t)i * 4);
        const int s0 = i * 4;
        const int sr = s0 / W1, sc = s0 % W1;       // 4 | W1: same sr for all 4
        const bool rok = (sr >= BRM) && (sr < H1 - BRM);
        if (!(rok && sc + 0 >= BRM && sc + 0 < W1 - BRM) || __uint_as_float(c.x) <= THR) c.x = 0xFFFFFFFFu;
        if (!(rok && sc + 1 >= BRM && sc + 1 < W1 - BRM) || __uint_as_float(c.y) <= THR) c.y = 0xFFFFFFFFu;
        if (!(rok && sc + 2 >= BRM && sc + 2 < W1 - BRM) || __uint_as_float(c.z) <= THR) c.z = 0xFFFFFFFFu;
        if (!(rok && sc + 3 >= BRM && sc + 3 < W1 - BRM) || __uint_as_float(c.w) <= THR) c.w = 0xFFFFFFFFu;
        *reinterpret_cast<uint4*>(&s_cm[s0]) = c;
    }
    __syncthreads();

    const uint4* cm4 = reinterpret_cast<const uint4*>(s_cm);

    // Warp w owns rows lA = lbase+w and lB = lbase+8+w.
    const int lA = lbase + w;
    const int lB = lbase + 8 + w;
    const int lcA = lA % W0, lcB = lB % W0;
    const bool aok = lr_ok && (lcA >= BRM) && (lcA < W0 - BRM);
    const bool bok = lr_ok && (lcB >= BRM) && (lcB < W0 - BRM);

    const float4* rowA = reinterpret_cast<const float4*>(conf + ((size_t)n * LSZ + lA) * SSZ);
    const float4* rowB = reinterpret_cast<const float4*>(conf + ((size_t)n * LSZ + lB) * SSZ);

    float mA = 0.f, bvA = 0.f; int bjA = 0;
    float mB = 0.f, bvB = 0.f; int bjB = 0;

    if (aok && bok) {
        float a0 = 0.f, a1 = 0.f, a2 = 0.f, a3 = 0.f;
        float b0 = 0.f, b1 = 0.f, b2 = 0.f, b3 = 0.f;
        #pragma unroll 4
        for (int k = 0; k < 37; ++k) {              // 37*32 = 1184 uniform
            const int i = lane + k * 32;
            const float4 va = rowA[i];
            const float4 vb = rowB[i];
            const uint4  c  = cm4[i];
            elem_upd(va, c, i * 4, a0, a1, a2, a3, bvA, bjA);
            elem_upd(vb, c, i * 4, b0, b1, b2, b3, bvB, bjB);
        }
        if (lane < 16) {                            // tail: 1184..1199
            const int i = 1184 + lane;
            const float4 va = rowA[i];
            const float4 vb = rowB[i];
            const uint4  c  = cm4[i];
            elem_upd(va, c, i * 4, a0, a1, a2, a3, bvA, bjA);
            elem_upd(vb, c, i * 4, b0, b1, b2, b3, bvB, bjB);
        }
        mA = fmaxf(fmaxf(a0, a1), fmaxf(a2, a3));
        mB = fmaxf(fmaxf(b0, b1), fmaxf(b2, b3));
    } else if (aok || bok) {
        const float4* row = aok ? rowA : rowB;
        float a0 = 0.f, a1 = 0.f, a2 = 0.f, a3 = 0.f;
        float bv = 0.f; int bj = 0;
        #pragma unroll 4
        for (int k = 0; k < 37; ++k) {
            const int i = lane + k * 32;
            elem_upd(row[i], cm4[i], i * 4, a0, a1, a2, a3, bv, bj);
        }
        if (lane < 16) {
            const int i = 1184 + lane;
            elem_upd(row[i], cm4[i], i * 4, a0, a1, a2, a3, bv, bj);
        }
        const float m = fmaxf(fmaxf(a0, a1), fmaxf(a2, a3));
        if (aok) { mA = m; bvA = bv; bjA = bj; }
        else     { mB = m; bvB = bv; bjB = bj; }
    }

    warp_reduce_row(mA, bvA, bjA);
    warp_reduce_row(mB, bvB, bjB);

    if (lane == 0) {
        {
            const int o = n * LSZ + lA;
            const bool hit = aok && (bvA > 0.f) && (bvA == mA);
            out[o]          = hit ? mA : 0.f;
            out[NL + o]     = hit ? 1.f : 0.f;
            out[2 * NL + o] = hit ? (float)bjA : 0.f;
        }
        {
            const int o = n * LSZ + lB;
            const bool hit = bok && (bvB > 0.f) && (bvB == mB);
            out[o]          = hit ? mB : 0.f;
            out[NL + o]     = hit ? 1.f : 0.f;
            out[2 * NL + o] = hit ? (float)bjB : 0.f;
        }
    }
}

extern "C" void kernel_launch(void* const* d_in, const int* in_sizes, int n_in,
                              void* d_out, int out_size) {
    const float* conf = (const float*)d_in[0];
    const long long total = (long long)in_sizes[0];
    int N = (int)(total / ((long long)LSZ * (long long)SSZ));
    if (N < 1) N = 1;
    if (N > MAXN) N = MAXN;

    void* cm_ptr = nullptr;
    cudaGetSymbolAddress(&cm_ptr, g_colmax);
    cudaMemsetAsync(cm_ptr, 0, (size_t)N * SSZ * sizeof(unsigned int));

    dim3 g1((NF4 + 255) / 256, LSZ / 100, N);       // (5, 48, N)
    colmax_kernel<<<g1, 256>>>(conf);

    match_kernel<<<N * (LSZ / RPB), 256>>>(conf, (float*)d_out, N);
}

// round 10
// speedup vs baseline: 2.1556x; 1.0969x over previous
#include <cuda_runtime.h>
#include <stdint.h>

// CoarseMatching, 2-pass, single-wave match over valid rows only.
// conf [N, L, S] fp32, L = 4800, S = 4800.
// Outputs (concatenated fp32): mconf [N*L], mask_v [N*L], all_j_ids [N*L].
//
// Pass 1 (colmax): full read, per-column max via atomicMax on float bits.
// Pass 2 (match): block-per-row scan (R5 structure) over l in [160,4640)
//   only (rows with valid lr). colmax staged in SMEM with border-invalid /
//   (<=THR) columns poisoned. Grid sized to fit in ONE wave (640 blocks).
//   Output pre-zeroed by memset; only hits are written.

#define THR  0.2f
#define BRM  2
#define H0   60
#define W0   80
#define H1   60
#define W1   80
#define LSZ  (H0 * W0)   // 4800
#define SSZ  (H1 * W1)   // 4800
#define MAXN 16
#define NF4  (SSZ / 4)   // 1200
#define RPB  28
#define VL0  (BRM * W0)              // 160: first valid-lr row
#define NVR  (LSZ - 2 * BRM * W0)    // 4480 valid-lr rows
#define GROUPS (NVR / RPB)           // 160
#define SLOTS 5

__device__ unsigned int g_colmax[MAXN * SSZ];

__global__ __launch_bounds__(256) void colmax_kernel(const float* __restrict__ conf) {
    const int n  = blockIdx.z;
    const int i4 = blockIdx.x * blockDim.x + threadIdx.x;
    if (i4 >= NF4) return;
    const int l0 = blockIdx.y * 100;

    const float4* p = reinterpret_cast<const float4*>(
        conf + ((size_t)n * LSZ + (size_t)l0) * SSZ) + i4;

    float4 m = make_float4(0.f, 0.f, 0.f, 0.f);
    #pragma unroll 5
    for (int t = 0; t < 100; ++t) {
        const float4 v = *p;
        m.x = fmaxf(m.x, v.x);
        m.y = fmaxf(m.y, v.y);
        m.z = fmaxf(m.z, v.z);
        m.w = fmaxf(m.w, v.w);
        p += NF4;
    }
    unsigned int* cm = g_colmax + (size_t)n * SSZ + (size_t)i4 * 4;
    atomicMax(cm + 0, __float_as_uint(m.x));
    atomicMax(cm + 1, __float_as_uint(m.y));
    atomicMax(cm + 2, __float_as_uint(m.z));
    atomicMax(cm + 3, __float_as_uint(m.w));
}

__global__ __launch_bounds__(256) void match_kernel(const float* __restrict__ conf,
                                                    float* __restrict__ out, int N) {
    __shared__ unsigned s_cm[SSZ];                  // 19.2 KB poisoned colmax
    __shared__ float s_m [RPB][8];
    __shared__ float s_bv[RPB][8];
    __shared__ int   s_bj[RPB][8];

    const int tid   = threadIdx.x;
    const int n     = blockIdx.x / GROUPS;
    const int lbase = VL0 + (blockIdx.x % GROUPS) * RPB;
    const int NL    = N * LSZ;
    const int w     = tid >> 5, lane = tid & 31;

    // Stage colmax into SMEM; poison border-invalid and <=THR columns with
    // 0xFFFFFFFF (unreachable by any conf bit pattern < 1.0f).
    #pragma unroll
    for (int k = 0; k < SLOTS; ++k) {
        const int i = tid + k * 256;
        if (k < SLOTS - 1 || i < NF4) {
            uint4 c = *reinterpret_cast<const uint4*>(
                g_colmax + (size_t)n * SSZ + (size_t)i * 4);
            const int s0 = i * 4;
            const int sr = s0 / W1, sc = s0 % W1;   // 4 | W1: same sr for all 4
            const bool rok = (sr >= BRM) && (sr < H1 - BRM);
            if (!(rok && sc + 0 >= BRM && sc + 0 < W1 - BRM) || __uint_as_float(c.x) <= THR) c.x = 0xFFFFFFFFu;
            if (!(rok && sc + 1 >= BRM && sc + 1 < W1 - BRM) || __uint_as_float(c.y) <= THR) c.y = 0xFFFFFFFFu;
            if (!(rok && sc + 2 >= BRM && sc + 2 < W1 - BRM) || __uint_as_float(c.z) <= THR) c.z = 0xFFFFFFFFu;
            if (!(rok && sc + 3 >= BRM && sc + 3 < W1 - BRM) || __uint_as_float(c.w) <= THR) c.w = 0xFFFFFFFFu;
            *reinterpret_cast<uint4*>(&s_cm[s0]) = c;
        }
    }
    __syncthreads();

    const uint4* cm4 = reinterpret_cast<const uint4*>(s_cm);

    #pragma unroll 1
    for (int r = 0; r < RPB; ++r) {
        const int l  = lbase + r;
        const int lc = l % W0;
        if (lc < BRM || lc >= W0 - BRM) continue;   // uniform across block

        const float4* row = reinterpret_cast<const float4*>(
            conf + ((size_t)n * LSZ + (size_t)l) * SSZ);

        float m0 = 0.f, m1 = 0.f, m2 = 0.f, m3 = 0.f;
        float bv = 0.f;
        int   bj = 0;

        #pragma unroll
        for (int k = 0; k < SLOTS; ++k) {
            const int i = tid + k * 256;
            if (k < SLOTS - 1 || i < NF4) {
                const float4 v = __ldcs(&row[i]);
                const uint4  c = cm4[i];
                m0 = fmaxf(m0, v.x);
                m1 = fmaxf(m1, v.y);
                m2 = fmaxf(m2, v.z);
                m3 = fmaxf(m3, v.w);
                const bool c0 = (__float_as_uint(v.x) == c.x);
                const bool c1 = (__float_as_uint(v.y) == c.y);
                const bool c2 = (__float_as_uint(v.z) == c.z);
                const bool c3 = (__float_as_uint(v.w) == c.w);
                if (c0 | c1 | c2 | c3) {            // rare (~1 per column)
                    const int s0 = i * 4;
                    if (c0 && v.x > bv) { bv = v.x; bj = s0 + 0; }
                    if (c1 && v.y > bv) { bv = v.y; bj = s0 + 1; }
                    if (c2 && v.z > bv) { bv = v.z; bj = s0 + 2; }
                    if (c3 && v.w > bv) { bv = v.w; bj = s0 + 3; }
                }
            }
        }

        float m = fmaxf(fmaxf(m0, m1), fmaxf(m2, m3));
        #pragma unroll
        for (int off = 16; off; off >>= 1) {
            m = fmaxf(m, __shfl_down_sync(0xFFFFFFFFu, m, off));
            const float ov = __shfl_down_sync(0xFFFFFFFFu, bv, off);
            const int   oj = __shfl_down_sync(0xFFFFFFFFu, bj, off);
            if (ov > bv || (ov == bv && oj < bj)) { bv = ov; bj = oj; }
        }
        if (lane == 0) {
            s_m [r][w] = m;
            s_bv[r][w] = bv;
            s_bj[r][w] = bj;
        }
    }

    __syncthreads();

    if (tid < RPB) {
        const int l  = lbase + tid;
        const int lc = l % W0;
        if (lc >= BRM && lc < W0 - BRM) {
            float m  = s_m [tid][0];
            float bv = s_bv[tid][0];
            int   bj = s_bj[tid][0];
            #pragma unroll
            for (int w2 = 1; w2 < 8; ++w2) {
                m = fmaxf(m, s_m[tid][w2]);
                const float ov = s_bv[tid][w2];
                const int   oj = s_bj[tid][w2];
                if (ov > bv || (ov == bv && oj < bj)) { bv = ov; bj = oj; }
            }
            if (bv > 0.f && bv == m) {              // matched: write (rest pre-zeroed)
                const int o = n * LSZ + l;
                out[o]          = m;
                out[NL + o]     = 1.f;
                out[2 * NL + o] = (float)bj;
            }
        }
    }
}

extern "C" void kernel_launch(void* const* d_in, const int* in_sizes, int n_in,
                              void* d_out, int out_size) {
    const float* conf = (const float*)d_in[0];
    const long long total = (long long)in_sizes[0];
    int N = (int)(total / ((long long)LSZ * (long long)SSZ));
    if (N < 1) N = 1;
    if (N > MAXN) N = MAXN;

    void* cm_ptr = nullptr;
    cudaGetSymbolAddress(&cm_ptr, g_colmax);
    cudaMemsetAsync(cm_ptr, 0, (size_t)N * SSZ * sizeof(unsigned int));
    cudaMemsetAsync(d_out, 0, (size_t)out_size * sizeof(float));

    dim3 g1((NF4 + 255) / 256, LSZ / 100, N);       // (5, 48, N)
    colmax_kernel<<<g1, 256>>>(conf);

    match_kernel<<<N * GROUPS, 256>>>(conf, (float*)d_out, N);   // 640 blocks
}